// round 3
// baseline (speedup 1.0000x reference)
#include <cuda_runtime.h>
#include <cstdint>

// Problem constants
#define B_  2
#define T_  2048
#define D_  2048
#define H_  16
#define HKV_ 4
#define DH_ 128
#define M_  (B_*T_)        // 4096 rows
#define NQ_ (H_*DH_)       // 2048
#define NKV_ (HKV_*DH_)    // 512

// Scratch (allocation-free rule: __device__ globals)
__device__ float g_q[(size_t)M_ * NQ_];    // [b,t,h,dh]
__device__ float g_k[(size_t)M_ * NKV_];   // [b,t,kvh,dh]
__device__ float g_v[(size_t)M_ * NKV_];   // [b,t,kvh,dh]
__device__ float g_att[(size_t)M_ * NQ_];  // [b,t,h*dh]

// ---------------------------------------------------------------------------
// NT SGEMM: C[m,n] = sum_k A[m,k] * W[n,k]
// A row-major [M,K], W row-major [N,K]. 128x128 tile, BK=8, 256 threads,
// 8x8 per thread. Cols mapped tx+16j -> conflict-free Ws reads, coalesced C.
// ---------------------------------------------------------------------------
__global__ __launch_bounds__(256, 2) void sgemm_nt(
    const float* __restrict__ A, const float* __restrict__ W,
    float* __restrict__ C, int M, int N, int K)
{
    __shared__ float As[8][132];
    __shared__ float Ws[8][132];

    const int tid = threadIdx.x;
    const int tx  = tid & 15;
    const int ty  = tid >> 4;
    const int row0 = blockIdx.y * 128;
    const int col0 = blockIdx.x * 128;

    const int lr = tid >> 1;          // 0..127
    const int lc = (tid & 1) << 2;    // 0 or 4
    const float* Ap = A + (size_t)(row0 + lr) * K + lc;
    const float* Wp = W + (size_t)(col0 + lr) * K + lc;

    float acc[8][8];
#pragma unroll
    for (int i = 0; i < 8; i++)
#pragma unroll
        for (int j = 0; j < 8; j++) acc[i][j] = 0.f;

    float4 av = *(const float4*)(Ap);
    float4 wv = *(const float4*)(Wp);

    for (int k0 = 0; k0 < K; k0 += 8) {
        __syncthreads();
        As[lc+0][lr] = av.x; As[lc+1][lr] = av.y;
        As[lc+2][lr] = av.z; As[lc+3][lr] = av.w;
        Ws[lc+0][lr] = wv.x; Ws[lc+1][lr] = wv.y;
        Ws[lc+2][lr] = wv.z; Ws[lc+3][lr] = wv.w;
        __syncthreads();

        if (k0 + 8 < K) {   // prefetch next tile while computing
            av = *(const float4*)(Ap + k0 + 8);
            wv = *(const float4*)(Wp + k0 + 8);
        }

#pragma unroll
        for (int kk = 0; kk < 8; kk++) {
            float a[8], bv[8];
            float4 a0 = *(const float4*)&As[kk][ty*8];
            float4 a1 = *(const float4*)&As[kk][ty*8+4];
            a[0]=a0.x; a[1]=a0.y; a[2]=a0.z; a[3]=a0.w;
            a[4]=a1.x; a[5]=a1.y; a[6]=a1.z; a[7]=a1.w;
#pragma unroll
            for (int j = 0; j < 8; j++) bv[j] = Ws[kk][tx + 16*j];
#pragma unroll
            for (int i = 0; i < 8; i++)
#pragma unroll
                for (int j = 0; j < 8; j++)
                    acc[i][j] += a[i] * bv[j];
        }
    }

#pragma unroll
    for (int i = 0; i < 8; i++) {
        float* Crow = C + (size_t)(row0 + ty*8 + i) * N + col0;
#pragma unroll
        for (int j = 0; j < 8; j++) Crow[tx + 16*j] = acc[i][j];
    }
}

// ---------------------------------------------------------------------------
// RoPE (interleaved pairs on first RD=64 dims) + temp fold into q.
// One block per token; covers H q-heads and HKV k-heads.
// ---------------------------------------------------------------------------
__global__ __launch_bounds__(256) void rope_kernel(
    float* __restrict__ q, float* __restrict__ k,
    const float* __restrict__ cosb, const float* __restrict__ sinb,
    const float* __restrict__ temp)
{
    const int token = blockIdx.x;       // b*T + t
    const int t = token & (T_ - 1);
    for (int s = threadIdx.x; s < (H_ + HKV_) * 64; s += blockDim.x) {
        const int head = s >> 6;
        const int i = s & 63;
        float* base;
        float scale;
        if (head < H_) {
            base = q + ((size_t)token * H_ + head) * DH_;
            scale = temp[head];
        } else {
            base = k + ((size_t)token * HKV_ + (head - H_)) * DH_;
            scale = 1.0f;
        }
        if (i < 32) {
            const float c  = cosb[t*32 + i];
            const float sn = sinb[t*32 + i];
            const float x1 = base[2*i];
            const float x2 = base[2*i + 1];
            base[2*i]     = (x1*c - x2*sn) * scale;
            base[2*i + 1] = (x1*sn + x2*c) * scale;
        } else {
            const int d = 64 + (i - 32) * 2;
            base[d]     *= scale;
            base[d + 1] *= scale;
        }
    }
}

// ---------------------------------------------------------------------------
// Causal GQA flash attention. BQ=64, BK=64, DH=128.
// 256 threads as 16x16 grid: S cols c=tx+16j, rows r=ty+16i.
// smem: Qs[64][132], KVs[64][132] (K then V), Ps[64][68]. 84992 B dynamic.
// ---------------------------------------------------------------------------
#define ATTN_SMEM_FLOATS (2*64*132 + 64*68)
#define ATTN_SMEM_BYTES  (ATTN_SMEM_FLOATS * 4)

__global__ __launch_bounds__(256, 2) void attn_kernel(
    const float* __restrict__ Qg, const float* __restrict__ Kg,
    const float* __restrict__ Vg, float* __restrict__ Og)
{
    extern __shared__ float sm[];
    float* Qs  = sm;                 // [64][132]
    float* KVs = sm + 64*132;        // [64][132]
    float* Ps  = sm + 2*64*132;      // [64][68]

    const int qt  = blockIdx.x;      // q tile 0..31
    const int h   = blockIdx.y;
    const int b   = blockIdx.z;
    const int kvh = h >> 2;          // REP = 4
    const int tid = threadIdx.x;
    const int tx  = tid & 15;
    const int ty  = tid >> 4;
    const int qrow0 = qt * 64;

    // Load Q tile
    const float* Qb = Qg + (((size_t)b*T_ + qrow0)*H_ + h)*DH_;
    for (int idx = tid; idx < 64*32; idx += 256) {
        const int r = idx >> 5, c4 = (idx & 31) << 2;
        *(float4*)&Qs[r*132 + c4] = *(const float4*)(Qb + (size_t)r*(H_*DH_) + c4);
    }

    float m_i[4], l_i[4], o[4][8];
#pragma unroll
    for (int i = 0; i < 4; i++) {
        m_i[i] = -3.0e38f; l_i[i] = 0.f;
#pragma unroll
        for (int j = 0; j < 8; j++) o[i][j] = 0.f;
    }

    const float scale = 0.08838834764831845f;   // 1/sqrt(128)

    for (int kt = 0; kt <= qt; kt++) {
        const size_t kvoff = (((size_t)b*T_ + kt*64)*HKV_ + kvh)*DH_;

        __syncthreads();   // prev V reads done (also covers Q load on iter 0)
        for (int idx = tid; idx < 64*32; idx += 256) {
            const int r = idx >> 5, c4 = (idx & 31) << 2;
            *(float4*)&KVs[r*132 + c4] =
                *(const float4*)(Kg + kvoff + (size_t)r*(HKV_*DH_) + c4);
        }
        __syncthreads();

        // S = Q K^T
        float s[4][4];
#pragma unroll
        for (int i = 0; i < 4; i++)
#pragma unroll
            for (int j = 0; j < 4; j++) s[i][j] = 0.f;

#pragma unroll 4
        for (int d = 0; d < DH_; d += 4) {
            float4 qv[4], kv[4];
#pragma unroll
            for (int i = 0; i < 4; i++)
                qv[i] = *(const float4*)&Qs[(ty + 16*i)*132 + d];
#pragma unroll
            for (int j = 0; j < 4; j++)
                kv[j] = *(const float4*)&KVs[(tx + 16*j)*132 + d];
#pragma unroll
            for (int i = 0; i < 4; i++)
#pragma unroll
                for (int j = 0; j < 4; j++) {
                    s[i][j] += qv[i].x * kv[j].x;
                    s[i][j] += qv[i].y * kv[j].y;
                    s[i][j] += qv[i].z * kv[j].z;
                    s[i][j] += qv[i].w * kv[j].w;
                }
        }

        // scale + causal mask (only diagonal tile needs the compare)
        if (kt == qt) {
#pragma unroll
            for (int i = 0; i < 4; i++)
#pragma unroll
                for (int j = 0; j < 4; j++) {
                    if (tx + 16*j > ty + 16*i) s[i][j] = -1e30f;
                    else s[i][j] *= scale;
                }
        } else {
#pragma unroll
            for (int i = 0; i < 4; i++)
#pragma unroll
                for (int j = 0; j < 4; j++) s[i][j] *= scale;
        }

        // online softmax per row (row shared by 16 tx lanes -> xor shuffle)
#pragma unroll
        for (int i = 0; i < 4; i++) {
            float rm = fmaxf(fmaxf(s[i][0], s[i][1]), fmaxf(s[i][2], s[i][3]));
#pragma unroll
            for (int off = 8; off > 0; off >>= 1)
                rm = fmaxf(rm, __shfl_xor_sync(0xffffffffu, rm, off));
            const float mnew = fmaxf(m_i[i], rm);
            const float al = __expf(m_i[i] - mnew);
            float rs = 0.f;
#pragma unroll
            for (int j = 0; j < 4; j++) {
                const float p = __expf(s[i][j] - mnew);
                s[i][j] = p;
                rs += p;
            }
#pragma unroll
            for (int off = 8; off > 0; off >>= 1)
                rs += __shfl_xor_sync(0xffffffffu, rs, off);
            l_i[i] = l_i[i] * al + rs;
            m_i[i] = mnew;
#pragma unroll
            for (int jj = 0; jj < 8; jj++) o[i][jj] *= al;
#pragma unroll
            for (int j = 0; j < 4; j++)
                Ps[(ty + 16*i)*68 + tx + 16*j] = s[i][j];
        }
        __syncthreads();   // K reads + P writes done before V overwrites KVs

        // Load V tile over KVs
        for (int idx = tid; idx < 64*32; idx += 256) {
            const int r = idx >> 5, c4 = (idx & 31) << 2;
            *(float4*)&KVs[r*132 + c4] =
                *(const float4*)(Vg + kvoff + (size_t)r*(HKV_*DH_) + c4);
        }
        __syncthreads();

        // O += P @ V   (O cols d = tx + 16*jj)
#pragma unroll 4
        for (int c = 0; c < 64; c++) {
            float pv[4];
#pragma unroll
            for (int i = 0; i < 4; i++) pv[i] = Ps[(ty + 16*i)*68 + c];
#pragma unroll
            for (int jj = 0; jj < 8; jj++) {
                const float vv = KVs[c*132 + tx + 16*jj];
#pragma unroll
                for (int i = 0; i < 4; i++) o[i][jj] += pv[i] * vv;
            }
        }
    }

    // epilogue: O / l  -> g_att [b,t, h*128+d]
#pragma unroll
    for (int i = 0; i < 4; i++) {
        const int t = qrow0 + ty + 16*i;
        const float inv = 1.f / l_i[i];
        float* orow = Og + ((size_t)b*T_ + t)*(H_*DH_) + h*DH_;
#pragma unroll
        for (int jj = 0; jj < 8; jj++)
            orow[tx + 16*jj] = o[i][jj] * inv;
    }
}

// ---------------------------------------------------------------------------
extern "C" void kernel_launch(void* const* d_in, const int* in_sizes, int n_in,
                              void* d_out, int out_size)
{
    const float* x    = (const float*)d_in[0];
    const float* cosb = (const float*)d_in[1];
    const float* sinb = (const float*)d_in[2];
    const float* Wq   = (const float*)d_in[3];
    const float* Wk   = (const float*)d_in[4];
    const float* Wv   = (const float*)d_in[5];
    const float* Wo   = (const float*)d_in[6];
    const float* temp = (const float*)d_in[7];
    float* out = (float*)d_out;

    float *q, *k, *v, *att;
    cudaGetSymbolAddress((void**)&q,   g_q);
    cudaGetSymbolAddress((void**)&k,   g_k);
    cudaGetSymbolAddress((void**)&v,   g_v);
    cudaGetSymbolAddress((void**)&att, g_att);

    // QKV projections
    sgemm_nt<<<dim3(NQ_/128,  M_/128), 256>>>(x, Wq, q, M_, NQ_,  D_);
    sgemm_nt<<<dim3(NKV_/128, M_/128), 256>>>(x, Wk, k, M_, NKV_, D_);
    sgemm_nt<<<dim3(NKV_/128, M_/128), 256>>>(x, Wv, v, M_, NKV_, D_);

    // RoPE + temp
    rope_kernel<<<M_, 256>>>(q, k, cosb, sinb, temp);

    // Flash attention
    cudaFuncSetAttribute(attn_kernel,
                         cudaFuncAttributeMaxDynamicSharedMemorySize,
                         ATTN_SMEM_BYTES);
    attn_kernel<<<dim3(T_/64, H_, B_), 256, ATTN_SMEM_BYTES>>>(q, k, v, att);

    // Output projection
    sgemm_nt<<<dim3(D_/128, M_/128), 256>>>(att, Wo, out, M_, D_, D_);
}

// round 4
// speedup vs baseline: 1.5393x; 1.5393x over previous
#include <cuda_runtime.h>
#include <cuda_bf16.h>
#include <cstdint>

// Problem constants
#define B_  2
#define T_  2048
#define D_  2048
#define H_  16
#define HKV_ 4
#define DH_ 128
#define M_  (B_*T_)        // 4096 rows
#define NQ_ (H_*DH_)       // 2048
#define NKV_ (HKV_*DH_)    // 512

// fp32 scratch
__device__ float g_q[(size_t)M_ * NQ_];    // [b,t,h,dh]
__device__ float g_k[(size_t)M_ * NKV_];
__device__ float g_v[(size_t)M_ * NKV_];
__device__ float g_att[(size_t)M_ * NQ_];

// bf16 split scratch (hi/lo)
__device__ __nv_bfloat16 g_xhi[(size_t)M_ * D_],  g_xlo[(size_t)M_ * D_];
__device__ __nv_bfloat16 g_qwhi[(size_t)NQ_ * D_], g_qwlo[(size_t)NQ_ * D_];
__device__ __nv_bfloat16 g_kwhi[(size_t)NKV_ * D_], g_kwlo[(size_t)NKV_ * D_];
__device__ __nv_bfloat16 g_vwhi[(size_t)NKV_ * D_], g_vwlo[(size_t)NKV_ * D_];
__device__ __nv_bfloat16 g_owhi[(size_t)D_ * D_],  g_owlo[(size_t)D_ * D_];
__device__ __nv_bfloat16 g_ahi[(size_t)M_ * NQ_],  g_alo[(size_t)M_ * NQ_];

// ---------------------------------------------------------------------------
// PTX helpers
// ---------------------------------------------------------------------------
__device__ __forceinline__ void cp_async16(uint32_t s, const void* g) {
    asm volatile("cp.async.cg.shared.global [%0], [%1], 16;\n" :: "r"(s), "l"(g));
}
__device__ __forceinline__ void cp_commit() {
    asm volatile("cp.async.commit_group;\n");
}
template<int N> __device__ __forceinline__ void cp_wait() {
    asm volatile("cp.async.wait_group %0;\n" :: "n"(N));
}
__device__ __forceinline__ void ldsm_x4(uint32_t& r0, uint32_t& r1,
                                        uint32_t& r2, uint32_t& r3, uint32_t a) {
    asm volatile("ldmatrix.sync.aligned.m8n8.x4.shared.b16 {%0,%1,%2,%3}, [%4];\n"
                 : "=r"(r0), "=r"(r1), "=r"(r2), "=r"(r3) : "r"(a));
}
__device__ __forceinline__ void mma_bf16(float* d, const uint32_t* a,
                                         uint32_t b0, uint32_t b1) {
    asm volatile(
        "mma.sync.aligned.m16n8k16.row.col.f32.bf16.bf16.f32 "
        "{%0,%1,%2,%3},{%4,%5,%6,%7},{%8,%9},{%0,%1,%2,%3};\n"
        : "+f"(d[0]), "+f"(d[1]), "+f"(d[2]), "+f"(d[3])
        : "r"(a[0]), "r"(a[1]), "r"(a[2]), "r"(a[3]), "r"(b0), "r"(b1));
}

// ---------------------------------------------------------------------------
// Split fp32 -> bf16 hi + lo  (x = hi + lo + O(2^-18 x))
// ---------------------------------------------------------------------------
__global__ __launch_bounds__(256) void split_kernel(
    const float* __restrict__ in, __nv_bfloat16* __restrict__ hi,
    __nv_bfloat16* __restrict__ lo, int n)
{
    int i = blockIdx.x * blockDim.x + threadIdx.x;
    if (i < n) {
        float v = in[i];
        __nv_bfloat16 h = __float2bfloat16(v);
        hi[i] = h;
        lo[i] = __float2bfloat16(v - __bfloat162float(h));
    }
}

// ---------------------------------------------------------------------------
// bf16x3 NT GEMM:  C[m,n] = sum_k A[m,k] * W[n,k]   (fp32 out)
//   C ~= Ahi*Whi + Ahi*Wlo + Alo*Whi
// 128x128 tile, BK=32, 256 threads (8 warps, 2x4), warp tile 64x32,
// mma.m16n8k16, cp.async 2-stage pipeline, ldmatrix, 80B smem row stride.
// ---------------------------------------------------------------------------
#define BK_G   32
#define LDSR   40                 // bf16 elems per smem row (80 bytes)
#define TILE_E (128*LDSR)         // elems per tile matrix
#define TILE_B (TILE_E*2)         // 10240 bytes
#define STAGE_B (4*TILE_B)        // Ahi,Alo,Whi,Wlo: 40960 bytes
#define GEMM_SMEM (2*STAGE_B)     // 81920 bytes

__device__ __forceinline__ void gemm_load_stage(
    uint32_t sa, const __nv_bfloat16* Ahi, const __nv_bfloat16* Alo,
    const __nv_bfloat16* Whi, const __nv_bfloat16* Wlo,
    int bm, int bn, int K, int k0, int tid)
{
#pragma unroll
    for (int half = 0; half < 2; half++) {
        const int idx = tid + half * 256;     // 0..511
        const int row = idx >> 2;             // 0..127
        const int c8  = (idx & 3) << 3;       // 0,8,16,24
        const size_t ga = (size_t)(bm + row) * K + k0 + c8;
        const size_t gw = (size_t)(bn + row) * K + k0 + c8;
        const uint32_t so = (uint32_t)(row * LDSR + c8) * 2;
        cp_async16(sa +            so, Ahi + ga);
        cp_async16(sa + TILE_B   + so, Alo + ga);
        cp_async16(sa + 2*TILE_B + so, Whi + gw);
        cp_async16(sa + 3*TILE_B + so, Wlo + gw);
    }
}

__global__ __launch_bounds__(256) void gemm_bf16x3(
    const __nv_bfloat16* __restrict__ Ahi, const __nv_bfloat16* __restrict__ Alo,
    const __nv_bfloat16* __restrict__ Whi, const __nv_bfloat16* __restrict__ Wlo,
    float* __restrict__ C, int M, int N, int K)
{
    extern __shared__ __nv_bfloat16 smg[];
    const int tid  = threadIdx.x;
    const int warp = tid >> 5, lane = tid & 31;
    const int wm = (warp >> 2) * 64;      // 0 or 64
    const int wn = (warp & 3) * 32;       // 0,32,64,96
    const int bm = blockIdx.y * 128;
    const int bn = blockIdx.x * 128;
    const uint32_t sbase = (uint32_t)__cvta_generic_to_shared(smg);

    float acc[4][4][4];
#pragma unroll
    for (int i = 0; i < 4; i++)
#pragma unroll
        for (int j = 0; j < 4; j++)
#pragma unroll
            for (int r = 0; r < 4; r++) acc[i][j][r] = 0.f;

    // ldmatrix per-thread address components
    const int arow = (lane & 7) + ((lane >> 3) & 1) * 8;   // A: row within 16
    const int acb  = ((lane >> 4) & 1) * 16;               // A: col byte
    const int brow = (lane & 7) + ((lane >> 4) & 1) * 8;   // B: n-row within 16
    const int bcb  = ((lane >> 3) & 1) * 16;               // B: col byte

    gemm_load_stage(sbase, Ahi, Alo, Whi, Wlo, bm, bn, K, 0, tid);
    cp_commit();

    const int NC = K / BK_G;
    for (int c = 0; c < NC; c++) {
        if (c + 1 < NC) {
            gemm_load_stage(sbase + ((c + 1) & 1) * STAGE_B,
                            Ahi, Alo, Whi, Wlo, bm, bn, K, (c + 1) * BK_G, tid);
            cp_commit();
            cp_wait<1>();
        } else {
            cp_wait<0>();
        }
        __syncthreads();

        const uint32_t base = sbase + (c & 1) * STAGE_B;
        const uint32_t aAhi = base;
        const uint32_t aAlo = base + TILE_B;
        const uint32_t aWhi = base + 2*TILE_B;
        const uint32_t aWlo = base + 3*TILE_B;

#pragma unroll
        for (int kh = 0; kh < 2; kh++) {
            const int kb = kh * 32;   // byte offset of k-half within row
            uint32_t bhi[4][2], blo[4][2];
#pragma unroll
            for (int jj = 0; jj < 2; jj++) {
                uint32_t ad = aWhi + (uint32_t)((wn + jj*16 + brow) * LDSR) * 2 + bcb + kb;
                ldsm_x4(bhi[2*jj][0], bhi[2*jj][1], bhi[2*jj+1][0], bhi[2*jj+1][1], ad);
                ad = aWlo + (uint32_t)((wn + jj*16 + brow) * LDSR) * 2 + bcb + kb;
                ldsm_x4(blo[2*jj][0], blo[2*jj][1], blo[2*jj+1][0], blo[2*jj+1][1], ad);
            }
            uint32_t a[4][4];
#pragma unroll
            for (int i = 0; i < 4; i++) {
                uint32_t ad = aAhi + (uint32_t)((wm + i*16 + arow) * LDSR) * 2 + acb + kb;
                ldsm_x4(a[i][0], a[i][1], a[i][2], a[i][3], ad);
            }
#pragma unroll
            for (int i = 0; i < 4; i++)
#pragma unroll
                for (int j = 0; j < 4; j++) {
                    mma_bf16(acc[i][j], a[i], bhi[j][0], bhi[j][1]);
                    mma_bf16(acc[i][j], a[i], blo[j][0], blo[j][1]);
                }
#pragma unroll
            for (int i = 0; i < 4; i++) {
                uint32_t ad = aAlo + (uint32_t)((wm + i*16 + arow) * LDSR) * 2 + acb + kb;
                ldsm_x4(a[i][0], a[i][1], a[i][2], a[i][3], ad);
            }
#pragma unroll
            for (int i = 0; i < 4; i++)
#pragma unroll
                for (int j = 0; j < 4; j++)
                    mma_bf16(acc[i][j], a[i], bhi[j][0], bhi[j][1]);
        }
        __syncthreads();
    }

    // Epilogue: fp32 store
    const int er = lane >> 2, ec = (lane & 3) * 2;
#pragma unroll
    for (int i = 0; i < 4; i++)
#pragma unroll
        for (int j = 0; j < 4; j++) {
            float* p0 = C + (size_t)(bm + wm + 16*i + er) * N + bn + wn + 8*j + ec;
            float* p1 = p0 + (size_t)8 * N;
            *(float2*)p0 = make_float2(acc[i][j][0], acc[i][j][1]);
            *(float2*)p1 = make_float2(acc[i][j][2], acc[i][j][3]);
        }
}

// ---------------------------------------------------------------------------
// RoPE (interleaved pairs on first RD=64 dims) + temp fold into q.
// ---------------------------------------------------------------------------
__global__ __launch_bounds__(256) void rope_kernel(
    float* __restrict__ q, float* __restrict__ k,
    const float* __restrict__ cosb, const float* __restrict__ sinb,
    const float* __restrict__ temp)
{
    const int token = blockIdx.x;
    const int t = token & (T_ - 1);
    for (int s = threadIdx.x; s < (H_ + HKV_) * 64; s += blockDim.x) {
        const int head = s >> 6;
        const int i = s & 63;
        float* base;
        float scale;
        if (head < H_) {
            base = q + ((size_t)token * H_ + head) * DH_;
            scale = temp[head];
        } else {
            base = k + ((size_t)token * HKV_ + (head - H_)) * DH_;
            scale = 1.0f;
        }
        if (i < 32) {
            const float c  = cosb[t*32 + i];
            const float sn = sinb[t*32 + i];
            const float x1 = base[2*i];
            const float x2 = base[2*i + 1];
            base[2*i]     = (x1*c - x2*sn) * scale;
            base[2*i + 1] = (x1*sn + x2*c) * scale;
        } else {
            const int d = 64 + (i - 32) * 2;
            base[d]     *= scale;
            base[d + 1] *= scale;
        }
    }
}

// ---------------------------------------------------------------------------
// Causal GQA flash attention (fp32 SIMT). BQ=64, BK=64, DH=128.
// ---------------------------------------------------------------------------
#define ATTN_SMEM_FLOATS (2*64*132 + 64*68)
#define ATTN_SMEM_BYTES  (ATTN_SMEM_FLOATS * 4)

__global__ __launch_bounds__(256, 2) void attn_kernel(
    const float* __restrict__ Qg, const float* __restrict__ Kg,
    const float* __restrict__ Vg, float* __restrict__ Og)
{
    extern __shared__ float sm[];
    float* Qs  = sm;
    float* KVs = sm + 64*132;
    float* Ps  = sm + 2*64*132;

    const int qt  = blockIdx.x;
    const int h   = blockIdx.y;
    const int b   = blockIdx.z;
    const int kvh = h >> 2;
    const int tid = threadIdx.x;
    const int tx  = tid & 15;
    const int ty  = tid >> 4;
    const int qrow0 = qt * 64;

    const float* Qb = Qg + (((size_t)b*T_ + qrow0)*H_ + h)*DH_;
    for (int idx = tid; idx < 64*32; idx += 256) {
        const int r = idx >> 5, c4 = (idx & 31) << 2;
        *(float4*)&Qs[r*132 + c4] = *(const float4*)(Qb + (size_t)r*(H_*DH_) + c4);
    }

    float m_i[4], l_i[4], o[4][8];
#pragma unroll
    for (int i = 0; i < 4; i++) {
        m_i[i] = -3.0e38f; l_i[i] = 0.f;
#pragma unroll
        for (int j = 0; j < 8; j++) o[i][j] = 0.f;
    }

    const float scale = 0.08838834764831845f;

    for (int kt = 0; kt <= qt; kt++) {
        const size_t kvoff = (((size_t)b*T_ + kt*64)*HKV_ + kvh)*DH_;

        __syncthreads();
        for (int idx = tid; idx < 64*32; idx += 256) {
            const int r = idx >> 5, c4 = (idx & 31) << 2;
            *(float4*)&KVs[r*132 + c4] =
                *(const float4*)(Kg + kvoff + (size_t)r*(HKV_*DH_) + c4);
        }
        __syncthreads();

        float s[4][4];
#pragma unroll
        for (int i = 0; i < 4; i++)
#pragma unroll
            for (int j = 0; j < 4; j++) s[i][j] = 0.f;

#pragma unroll 4
        for (int d = 0; d < DH_; d += 4) {
            float4 qv[4], kv[4];
#pragma unroll
            for (int i = 0; i < 4; i++)
                qv[i] = *(const float4*)&Qs[(ty + 16*i)*132 + d];
#pragma unroll
            for (int j = 0; j < 4; j++)
                kv[j] = *(const float4*)&KVs[(tx + 16*j)*132 + d];
#pragma unroll
            for (int i = 0; i < 4; i++)
#pragma unroll
                for (int j = 0; j < 4; j++) {
                    s[i][j] += qv[i].x * kv[j].x;
                    s[i][j] += qv[i].y * kv[j].y;
                    s[i][j] += qv[i].z * kv[j].z;
                    s[i][j] += qv[i].w * kv[j].w;
                }
        }

        if (kt == qt) {
#pragma unroll
            for (int i = 0; i < 4; i++)
#pragma unroll
                for (int j = 0; j < 4; j++) {
                    if (tx + 16*j > ty + 16*i) s[i][j] = -1e30f;
                    else s[i][j] *= scale;
                }
        } else {
#pragma unroll
            for (int i = 0; i < 4; i++)
#pragma unroll
                for (int j = 0; j < 4; j++) s[i][j] *= scale;
        }

#pragma unroll
        for (int i = 0; i < 4; i++) {
            float rm = fmaxf(fmaxf(s[i][0], s[i][1]), fmaxf(s[i][2], s[i][3]));
#pragma unroll
            for (int off = 8; off > 0; off >>= 1)
                rm = fmaxf(rm, __shfl_xor_sync(0xffffffffu, rm, off));
            const float mnew = fmaxf(m_i[i], rm);
            const float al = __expf(m_i[i] - mnew);
            float rs = 0.f;
#pragma unroll
            for (int j = 0; j < 4; j++) {
                const float p = __expf(s[i][j] - mnew);
                s[i][j] = p;
                rs += p;
            }
#pragma unroll
            for (int off = 8; off > 0; off >>= 1)
                rs += __shfl_xor_sync(0xffffffffu, rs, off);
            l_i[i] = l_i[i] * al + rs;
            m_i[i] = mnew;
#pragma unroll
            for (int jj = 0; jj < 8; jj++) o[i][jj] *= al;
#pragma unroll
            for (int j = 0; j < 4; j++)
                Ps[(ty + 16*i)*68 + tx + 16*j] = s[i][j];
        }
        __syncthreads();

        for (int idx = tid; idx < 64*32; idx += 256) {
            const int r = idx >> 5, c4 = (idx & 31) << 2;
            *(float4*)&KVs[r*132 + c4] =
                *(const float4*)(Vg + kvoff + (size_t)r*(HKV_*DH_) + c4);
        }
        __syncthreads();

#pragma unroll 4
        for (int c = 0; c < 64; c++) {
            float pv[4];
#pragma unroll
            for (int i = 0; i < 4; i++) pv[i] = Ps[(ty + 16*i)*68 + c];
#pragma unroll
            for (int jj = 0; jj < 8; jj++) {
                const float vv = KVs[c*132 + tx + 16*jj];
#pragma unroll
                for (int i = 0; i < 4; i++) o[i][jj] += pv[i] * vv;
            }
        }
    }

#pragma unroll
    for (int i = 0; i < 4; i++) {
        const int t = qrow0 + ty + 16*i;
        const float inv = 1.f / l_i[i];
        float* orow = Og + ((size_t)b*T_ + t)*(H_*DH_) + h*DH_;
#pragma unroll
        for (int jj = 0; jj < 8; jj++)
            orow[tx + 16*jj] = o[i][jj] * inv;
    }
}

// ---------------------------------------------------------------------------
extern "C" void kernel_launch(void* const* d_in, const int* in_sizes, int n_in,
                              void* d_out, int out_size)
{
    const float* x    = (const float*)d_in[0];
    const float* cosb = (const float*)d_in[1];
    const float* sinb = (const float*)d_in[2];
    const float* Wq   = (const float*)d_in[3];
    const float* Wk   = (const float*)d_in[4];
    const float* Wv   = (const float*)d_in[5];
    const float* Wo   = (const float*)d_in[6];
    const float* temp = (const float*)d_in[7];
    float* out = (float*)d_out;

    float *q, *k, *v, *att;
    cudaGetSymbolAddress((void**)&q,   g_q);
    cudaGetSymbolAddress((void**)&k,   g_k);
    cudaGetSymbolAddress((void**)&v,   g_v);
    cudaGetSymbolAddress((void**)&att, g_att);

    __nv_bfloat16 *xhi, *xlo, *qwhi, *qwlo, *kwhi, *kwlo, *vwhi, *vwlo,
                  *owhi, *owlo, *ahi, *alo;
    cudaGetSymbolAddress((void**)&xhi,  g_xhi);
    cudaGetSymbolAddress((void**)&xlo,  g_xlo);
    cudaGetSymbolAddress((void**)&qwhi, g_qwhi);
    cudaGetSymbolAddress((void**)&qwlo, g_qwlo);
    cudaGetSymbolAddress((void**)&kwhi, g_kwhi);
    cudaGetSymbolAddress((void**)&kwlo, g_kwlo);
    cudaGetSymbolAddress((void**)&vwhi, g_vwhi);
    cudaGetSymbolAddress((void**)&vwlo, g_vwlo);
    cudaGetSymbolAddress((void**)&owhi, g_owhi);
    cudaGetSymbolAddress((void**)&owlo, g_owlo);
    cudaGetSymbolAddress((void**)&ahi,  g_ahi);
    cudaGetSymbolAddress((void**)&alo,  g_alo);

    cudaFuncSetAttribute(gemm_bf16x3,
                         cudaFuncAttributeMaxDynamicSharedMemorySize, GEMM_SMEM);
    cudaFuncSetAttribute(attn_kernel,
                         cudaFuncAttributeMaxDynamicSharedMemorySize, ATTN_SMEM_BYTES);

    // Split inputs to bf16 hi/lo
    split_kernel<<<(M_*D_ + 255)/256,   256>>>(x,  xhi,  xlo,  M_*D_);
    split_kernel<<<(NQ_*D_ + 255)/256,  256>>>(Wq, qwhi, qwlo, NQ_*D_);
    split_kernel<<<(NKV_*D_ + 255)/256, 256>>>(Wk, kwhi, kwlo, NKV_*D_);
    split_kernel<<<(NKV_*D_ + 255)/256, 256>>>(Wv, vwhi, vwlo, NKV_*D_);
    split_kernel<<<(D_*D_ + 255)/256,   256>>>(Wo, owhi, owlo, D_*D_);

    // QKV projections (tensor cores)
    gemm_bf16x3<<<dim3(NQ_/128,  M_/128), 256, GEMM_SMEM>>>(xhi, xlo, qwhi, qwlo, q, M_, NQ_,  D_);
    gemm_bf16x3<<<dim3(NKV_/128, M_/128), 256, GEMM_SMEM>>>(xhi, xlo, kwhi, kwlo, k, M_, NKV_, D_);
    gemm_bf16x3<<<dim3(NKV_/128, M_/128), 256, GEMM_SMEM>>>(xhi, xlo, vwhi, vwlo, v, M_, NKV_, D_);

    // RoPE + temp
    rope_kernel<<<M_, 256>>>(q, k, cosb, sinb, temp);

    // Flash attention (fp32)
    attn_kernel<<<dim3(T_/64, H_, B_), 256, ATTN_SMEM_BYTES>>>(q, k, v, att);

    // Output projection (tensor cores)
    split_kernel<<<(M_*NQ_ + 255)/256, 256>>>(att, ahi, alo, M_*NQ_);
    gemm_bf16x3<<<dim3(D_/128, M_/128), 256, GEMM_SMEM>>>(ahi, alo, owhi, owlo, out, M_, D_, D_);
}

// round 6
// speedup vs baseline: 1.5437x; 1.0029x over previous
#include <cuda_runtime.h>
#include <cuda_bf16.h>
#include <cstdint>

// Problem constants
#define B_  2
#define T_  2048
#define D_  2048
#define H_  16
#define HKV_ 4
#define DH_ 128
#define M_  (B_*T_)        // 4096 rows
#define NQ_ (H_*DH_)       // 2048
#define NKV_ (HKV_*DH_)    // 512

// fp32 scratch
__device__ float g_q[(size_t)M_ * NQ_];    // [b,t,h,dh]
__device__ float g_k[(size_t)M_ * NKV_];
__device__ float g_v[(size_t)M_ * NKV_];
__device__ float g_att[(size_t)M_ * NQ_];

// bf16 split scratch (hi/lo)
__device__ __nv_bfloat16 g_xhi[(size_t)M_ * D_],  g_xlo[(size_t)M_ * D_];
__device__ __nv_bfloat16 g_qwhi[(size_t)NQ_ * D_], g_qwlo[(size_t)NQ_ * D_];
__device__ __nv_bfloat16 g_kwhi[(size_t)NKV_ * D_], g_kwlo[(size_t)NKV_ * D_];
__device__ __nv_bfloat16 g_vwhi[(size_t)NKV_ * D_], g_vwlo[(size_t)NKV_ * D_];
__device__ __nv_bfloat16 g_owhi[(size_t)D_ * D_],  g_owlo[(size_t)D_ * D_];
__device__ __nv_bfloat16 g_ahi[(size_t)M_ * NQ_],  g_alo[(size_t)M_ * NQ_];

// ---------------------------------------------------------------------------
// PTX helpers
// ---------------------------------------------------------------------------
__device__ __forceinline__ void cp_async16(uint32_t s, const void* g) {
    asm volatile("cp.async.cg.shared.global [%0], [%1], 16;\n" :: "r"(s), "l"(g));
}
__device__ __forceinline__ void cp_commit() {
    asm volatile("cp.async.commit_group;\n");
}
template<int N> __device__ __forceinline__ void cp_wait() {
    asm volatile("cp.async.wait_group %0;\n" :: "n"(N));
}
__device__ __forceinline__ void ldsm_x4(uint32_t& r0, uint32_t& r1,
                                        uint32_t& r2, uint32_t& r3, uint32_t a) {
    asm volatile("ldmatrix.sync.aligned.m8n8.x4.shared.b16 {%0,%1,%2,%3}, [%4];\n"
                 : "=r"(r0), "=r"(r1), "=r"(r2), "=r"(r3) : "r"(a));
}
__device__ __forceinline__ void mma_bf16(float* d, const uint32_t* a,
                                         uint32_t b0, uint32_t b1) {
    asm volatile(
        "mma.sync.aligned.m16n8k16.row.col.f32.bf16.bf16.f32 "
        "{%0,%1,%2,%3},{%4,%5,%6,%7},{%8,%9},{%0,%1,%2,%3};\n"
        : "+f"(d[0]), "+f"(d[1]), "+f"(d[2]), "+f"(d[3])
        : "r"(a[0]), "r"(a[1]), "r"(a[2]), "r"(a[3]), "r"(b0), "r"(b1));
}

// ---------------------------------------------------------------------------
// Split fp32 -> bf16 hi + lo  (x = hi + lo + O(2^-18 x))
// ---------------------------------------------------------------------------
__global__ __launch_bounds__(256) void split_kernel(
    const float* __restrict__ in, __nv_bfloat16* __restrict__ hi,
    __nv_bfloat16* __restrict__ lo, int n)
{
    int i = blockIdx.x * blockDim.x + threadIdx.x;
    if (i < n) {
        float v = in[i];
        __nv_bfloat16 h = __float2bfloat16(v);
        hi[i] = h;
        lo[i] = __float2bfloat16(v - __bfloat162float(h));
    }
}

// ---------------------------------------------------------------------------
// bf16x3 NT GEMM:  C[m,n] = sum_k A[m,k] * W[n,k]   (fp32 out)
//   C ~= Ahi*Whi + Ahi*Wlo + Alo*Whi
// 128x128 tile, BK=32, 256 threads (8 warps, 2x4), warp tile 64x32,
// mma.m16n8k16, cp.async 2-stage pipeline, ldmatrix, 80B smem row stride.
// ---------------------------------------------------------------------------
#define BK_G   32
#define LDSR   40                 // bf16 elems per smem row (80 bytes)
#define TILE_E (128*LDSR)         // elems per tile matrix
#define TILE_B (TILE_E*2)         // 10240 bytes
#define STAGE_B (4*TILE_B)        // Ahi,Alo,Whi,Wlo: 40960 bytes
#define GEMM_SMEM (2*STAGE_B)     // 81920 bytes

__device__ __forceinline__ void gemm_load_stage(
    uint32_t sa, const __nv_bfloat16* Ahi, const __nv_bfloat16* Alo,
    const __nv_bfloat16* Whi, const __nv_bfloat16* Wlo,
    int bm, int bn, int K, int k0, int tid)
{
#pragma unroll
    for (int half = 0; half < 2; half++) {
        const int idx = tid + half * 256;     // 0..511
        const int row = idx >> 2;             // 0..127
        const int c8  = (idx & 3) << 3;       // 0,8,16,24
        const size_t ga = (size_t)(bm + row) * K + k0 + c8;
        const size_t gw = (size_t)(bn + row) * K + k0 + c8;
        const uint32_t so = (uint32_t)(row * LDSR + c8) * 2;
        cp_async16(sa +            so, Ahi + ga);
        cp_async16(sa + TILE_B   + so, Alo + ga);
        cp_async16(sa + 2*TILE_B + so, Whi + gw);
        cp_async16(sa + 3*TILE_B + so, Wlo + gw);
    }
}

__global__ __launch_bounds__(256) void gemm_bf16x3(
    const __nv_bfloat16* __restrict__ Ahi, const __nv_bfloat16* __restrict__ Alo,
    const __nv_bfloat16* __restrict__ Whi, const __nv_bfloat16* __restrict__ Wlo,
    float* __restrict__ C, int M, int N, int K)
{
    extern __shared__ __nv_bfloat16 smg[];
    const int tid  = threadIdx.x;
    const int warp = tid >> 5, lane = tid & 31;
    const int wm = (warp >> 2) * 64;      // 0 or 64
    const int wn = (warp & 3) * 32;       // 0,32,64,96
    const int bm = blockIdx.y * 128;
    const int bn = blockIdx.x * 128;
    const uint32_t sbase = (uint32_t)__cvta_generic_to_shared(smg);

    float acc[4][4][4];
#pragma unroll
    for (int i = 0; i < 4; i++)
#pragma unroll
        for (int j = 0; j < 4; j++)
#pragma unroll
            for (int r = 0; r < 4; r++) acc[i][j][r] = 0.f;

    // ldmatrix per-thread address components
    const int arow = (lane & 7) + ((lane >> 3) & 1) * 8;   // A: row within 16
    const int acb  = ((lane >> 4) & 1) * 16;               // A: col byte
    const int brow = (lane & 7) + ((lane >> 4) & 1) * 8;   // B: n-row within 16
    const int bcb  = ((lane >> 3) & 1) * 16;               // B: col byte

    gemm_load_stage(sbase, Ahi, Alo, Whi, Wlo, bm, bn, K, 0, tid);
    cp_commit();

    const int NC = K / BK_G;
    for (int c = 0; c < NC; c++) {
        if (c + 1 < NC) {
            gemm_load_stage(sbase + ((c + 1) & 1) * STAGE_B,
                            Ahi, Alo, Whi, Wlo, bm, bn, K, (c + 1) * BK_G, tid);
            cp_commit();
            cp_wait<1>();
        } else {
            cp_wait<0>();
        }
        __syncthreads();

        const uint32_t base = sbase + (c & 1) * STAGE_B;
        const uint32_t aAhi = base;
        const uint32_t aAlo = base + TILE_B;
        const uint32_t aWhi = base + 2*TILE_B;
        const uint32_t aWlo = base + 3*TILE_B;

#pragma unroll
        for (int kh = 0; kh < 2; kh++) {
            const int kb = kh * 32;   // byte offset of k-half within row
            uint32_t bhi[4][2], blo[4][2];
#pragma unroll
            for (int jj = 0; jj < 2; jj++) {
                uint32_t ad = aWhi + (uint32_t)((wn + jj*16 + brow) * LDSR) * 2 + bcb + kb;
                ldsm_x4(bhi[2*jj][0], bhi[2*jj][1], bhi[2*jj+1][0], bhi[2*jj+1][1], ad);
                ad = aWlo + (uint32_t)((wn + jj*16 + brow) * LDSR) * 2 + bcb + kb;
                ldsm_x4(blo[2*jj][0], blo[2*jj][1], blo[2*jj+1][0], blo[2*jj+1][1], ad);
            }
            uint32_t a[4][4];
#pragma unroll
            for (int i = 0; i < 4; i++) {
                uint32_t ad = aAhi + (uint32_t)((wm + i*16 + arow) * LDSR) * 2 + acb + kb;
                ldsm_x4(a[i][0], a[i][1], a[i][2], a[i][3], ad);
            }
#pragma unroll
            for (int i = 0; i < 4; i++)
#pragma unroll
                for (int j = 0; j < 4; j++) {
                    mma_bf16(acc[i][j], a[i], bhi[j][0], bhi[j][1]);
                    mma_bf16(acc[i][j], a[i], blo[j][0], blo[j][1]);
                }
#pragma unroll
            for (int i = 0; i < 4; i++) {
                uint32_t ad = aAlo + (uint32_t)((wm + i*16 + arow) * LDSR) * 2 + acb + kb;
                ldsm_x4(a[i][0], a[i][1], a[i][2], a[i][3], ad);
            }
#pragma unroll
            for (int i = 0; i < 4; i++)
#pragma unroll
                for (int j = 0; j < 4; j++)
                    mma_bf16(acc[i][j], a[i], bhi[j][0], bhi[j][1]);
        }
        __syncthreads();
    }

    // Epilogue: fp32 store
    const int er = lane >> 2, ec = (lane & 3) * 2;
#pragma unroll
    for (int i = 0; i < 4; i++)
#pragma unroll
        for (int j = 0; j < 4; j++) {
            float* p0 = C + (size_t)(bm + wm + 16*i + er) * N + bn + wn + 8*j + ec;
            float* p1 = p0 + (size_t)8 * N;
            *(float2*)p0 = make_float2(acc[i][j][0], acc[i][j][1]);
            *(float2*)p1 = make_float2(acc[i][j][2], acc[i][j][3]);
        }
}

// ---------------------------------------------------------------------------
// RoPE (interleaved pairs on first RD=64 dims) + temp fold into q.
// ---------------------------------------------------------------------------
__global__ __launch_bounds__(256) void rope_kernel(
    float* __restrict__ q, float* __restrict__ k,
    const float* __restrict__ cosb, const float* __restrict__ sinb,
    const float* __restrict__ temp)
{
    const int token = blockIdx.x;
    const int t = token & (T_ - 1);
    for (int s = threadIdx.x; s < (H_ + HKV_) * 64; s += blockDim.x) {
        const int head = s >> 6;
        const int i = s & 63;
        float* base;
        float scale;
        if (head < H_) {
            base = q + ((size_t)token * H_ + head) * DH_;
            scale = temp[head];
        } else {
            base = k + ((size_t)token * HKV_ + (head - H_)) * DH_;
            scale = 1.0f;
        }
        if (i < 32) {
            const float c  = cosb[t*32 + i];
            const float sn = sinb[t*32 + i];
            const float x1 = base[2*i];
            const float x2 = base[2*i + 1];
            base[2*i]     = (x1*c - x2*sn) * scale;
            base[2*i + 1] = (x1*sn + x2*c) * scale;
        } else {
            const int d = 64 + (i - 32) * 2;
            base[d]     *= scale;
            base[d + 1] *= scale;
        }
    }
}

// ---------------------------------------------------------------------------
// Causal GQA flash attention (fp32 SIMT). BQ=64, BK=64, DH=128.
// ---------------------------------------------------------------------------
#define ATTN_SMEM_FLOATS (2*64*132 + 64*68)
#define ATTN_SMEM_BYTES  (ATTN_SMEM_FLOATS * 4)

__global__ __launch_bounds__(256, 2) void attn_kernel(
    const float* __restrict__ Qg, const float* __restrict__ Kg,
    const float* __restrict__ Vg, float* __restrict__ Og)
{
    extern __shared__ float sm[];
    float* Qs  = sm;
    float* KVs = sm + 64*132;
    float* Ps  = sm + 2*64*132;

    const int qt  = blockIdx.x;
    const int h   = blockIdx.y;
    const int b   = blockIdx.z;
    const int kvh = h >> 2;
    const int tid = threadIdx.x;
    const int tx  = tid & 15;
    const int ty  = tid >> 4;
    const int qrow0 = qt * 64;

    const float* Qb = Qg + (((size_t)b*T_ + qrow0)*H_ + h)*DH_;
    for (int idx = tid; idx < 64*32; idx += 256) {
        const int r = idx >> 5, c4 = (idx & 31) << 2;
        *(float4*)&Qs[r*132 + c4] = *(const float4*)(Qb + (size_t)r*(H_*DH_) + c4);
    }

    float m_i[4], l_i[4], o[4][8];
#pragma unroll
    for (int i = 0; i < 4; i++) {
        m_i[i] = -3.0e38f; l_i[i] = 0.f;
#pragma unroll
        for (int j = 0; j < 8; j++) o[i][j] = 0.f;
    }

    const float scale = 0.08838834764831845f;

    for (int kt = 0; kt <= qt; kt++) {
        const size_t kvoff = (((size_t)b*T_ + kt*64)*HKV_ + kvh)*DH_;

        __syncthreads();
        for (int idx = tid; idx < 64*32; idx += 256) {
            const int r = idx >> 5, c4 = (idx & 31) << 2;
            *(float4*)&KVs[r*132 + c4] =
                *(const float4*)(Kg + kvoff + (size_t)r*(HKV_*DH_) + c4);
        }
        __syncthreads();

        float s[4][4];
#pragma unroll
        for (int i = 0; i < 4; i++)
#pragma unroll
            for (int j = 0; j < 4; j++) s[i][j] = 0.f;

#pragma unroll 4
        for (int d = 0; d < DH_; d += 4) {
            float4 qv[4], kv[4];
#pragma unroll
            for (int i = 0; i < 4; i++)
                qv[i] = *(const float4*)&Qs[(ty + 16*i)*132 + d];
#pragma unroll
            for (int j = 0; j < 4; j++)
                kv[j] = *(const float4*)&KVs[(tx + 16*j)*132 + d];
#pragma unroll
            for (int i = 0; i < 4; i++)
#pragma unroll
                for (int j = 0; j < 4; j++) {
                    s[i][j] += qv[i].x * kv[j].x;
                    s[i][j] += qv[i].y * kv[j].y;
                    s[i][j] += qv[i].z * kv[j].z;
                    s[i][j] += qv[i].w * kv[j].w;
                }
        }

        if (kt == qt) {
#pragma unroll
            for (int i = 0; i < 4; i++)
#pragma unroll
                for (int j = 0; j < 4; j++) {
                    if (tx + 16*j > ty + 16*i) s[i][j] = -1e30f;
                    else s[i][j] *= scale;
                }
        } else {
#pragma unroll
            for (int i = 0; i < 4; i++)
#pragma unroll
                for (int j = 0; j < 4; j++) s[i][j] *= scale;
        }

#pragma unroll
        for (int i = 0; i < 4; i++) {
            float rm = fmaxf(fmaxf(s[i][0], s[i][1]), fmaxf(s[i][2], s[i][3]));
#pragma unroll
            for (int off = 8; off > 0; off >>= 1)
                rm = fmaxf(rm, __shfl_xor_sync(0xffffffffu, rm, off));
            const float mnew = fmaxf(m_i[i], rm);
            const float al = __expf(m_i[i] - mnew);
            float rs = 0.f;
#pragma unroll
            for (int j = 0; j < 4; j++) {
                const float p = __expf(s[i][j] - mnew);
                s[i][j] = p;
                rs += p;
            }
#pragma unroll
            for (int off = 8; off > 0; off >>= 1)
                rs += __shfl_xor_sync(0xffffffffu, rs, off);
            l_i[i] = l_i[i] * al + rs;
            m_i[i] = mnew;
#pragma unroll
            for (int jj = 0; jj < 8; jj++) o[i][jj] *= al;
#pragma unroll
            for (int j = 0; j < 4; j++)
                Ps[(ty + 16*i)*68 + tx + 16*j] = s[i][j];
        }
        __syncthreads();

        for (int idx = tid; idx < 64*32; idx += 256) {
            const int r = idx >> 5, c4 = (idx & 31) << 2;
            *(float4*)&KVs[r*132 + c4] =
                *(const float4*)(Vg + kvoff + (size_t)r*(HKV_*DH_) + c4);
        }
        __syncthreads();

#pragma unroll 4
        for (int c = 0; c < 64; c++) {
            float pv[4];
#pragma unroll
            for (int i = 0; i < 4; i++) pv[i] = Ps[(ty + 16*i)*68 + c];
#pragma unroll
            for (int jj = 0; jj < 8; jj++) {
                const float vv = KVs[c*132 + tx + 16*jj];
#pragma unroll
                for (int i = 0; i < 4; i++) o[i][jj] += pv[i] * vv;
            }
        }
    }

#pragma unroll
    for (int i = 0; i < 4; i++) {
        const int t = qrow0 + ty + 16*i;
        const float inv = 1.f / l_i[i];
        float* orow = Og + ((size_t)b*T_ + t)*(H_*DH_) + h*DH_;
#pragma unroll
        for (int jj = 0; jj < 8; jj++)
            orow[tx + 16*jj] = o[i][jj] * inv;
    }
}

// ---------------------------------------------------------------------------
extern "C" void kernel_launch(void* const* d_in, const int* in_sizes, int n_in,
                              void* d_out, int out_size)
{
    const float* x    = (const float*)d_in[0];
    const float* cosb = (const float*)d_in[1];
    const float* sinb = (const float*)d_in[2];
    const float* Wq   = (const float*)d_in[3];
    const float* Wk   = (const float*)d_in[4];
    const float* Wv   = (const float*)d_in[5];
    const float* Wo   = (const float*)d_in[6];
    const float* temp = (const float*)d_in[7];
    float* out = (float*)d_out;

    float *q, *k, *v, *att;
    cudaGetSymbolAddress((void**)&q,   g_q);
    cudaGetSymbolAddress((void**)&k,   g_k);
    cudaGetSymbolAddress((void**)&v,   g_v);
    cudaGetSymbolAddress((void**)&att, g_att);

    __nv_bfloat16 *xhi, *xlo, *qwhi, *qwlo, *kwhi, *kwlo, *vwhi, *vwlo,
                  *owhi, *owlo, *ahi, *alo;
    cudaGetSymbolAddress((void**)&xhi,  g_xhi);
    cudaGetSymbolAddress((void**)&xlo,  g_xlo);
    cudaGetSymbolAddress((void**)&qwhi, g_qwhi);
    cudaGetSymbolAddress((void**)&qwlo, g_qwlo);
    cudaGetSymbolAddress((void**)&kwhi, g_kwhi);
    cudaGetSymbolAddress((void**)&kwlo, g_kwlo);
    cudaGetSymbolAddress((void**)&vwhi, g_vwhi);
    cudaGetSymbolAddress((void**)&vwlo, g_vwlo);
    cudaGetSymbolAddress((void**)&owhi, g_owhi);
    cudaGetSymbolAddress((void**)&owlo, g_owlo);
    cudaGetSymbolAddress((void**)&ahi,  g_ahi);
    cudaGetSymbolAddress((void**)&alo,  g_alo);

    cudaFuncSetAttribute(gemm_bf16x3,
                         cudaFuncAttributeMaxDynamicSharedMemorySize, GEMM_SMEM);
    cudaFuncSetAttribute(attn_kernel,
                         cudaFuncAttributeMaxDynamicSharedMemorySize, ATTN_SMEM_BYTES);

    // Split inputs to bf16 hi/lo
    split_kernel<<<(M_*D_ + 255)/256,   256>>>(x,  xhi,  xlo,  M_*D_);
    split_kernel<<<(NQ_*D_ + 255)/256,  256>>>(Wq, qwhi, qwlo, NQ_*D_);
    split_kernel<<<(NKV_*D_ + 255)/256, 256>>>(Wk, kwhi, kwlo, NKV_*D_);
    split_kernel<<<(NKV_*D_ + 255)/256, 256>>>(Wv, vwhi, vwlo, NKV_*D_);
    split_kernel<<<(D_*D_ + 255)/256,   256>>>(Wo, owhi, owlo, D_*D_);

    // QKV projections (tensor cores)
    gemm_bf16x3<<<dim3(NQ_/128,  M_/128), 256, GEMM_SMEM>>>(xhi, xlo, qwhi, qwlo, q, M_, NQ_,  D_);
    gemm_bf16x3<<<dim3(NKV_/128, M_/128), 256, GEMM_SMEM>>>(xhi, xlo, kwhi, kwlo, k, M_, NKV_, D_);
    gemm_bf16x3<<<dim3(NKV_/128, M_/128), 256, GEMM_SMEM>>>(xhi, xlo, vwhi, vwlo, v, M_, NKV_, D_);

    // RoPE + temp
    rope_kernel<<<M_, 256>>>(q, k, cosb, sinb, temp);

    // Flash attention (fp32)
    attn_kernel<<<dim3(T_/64, H_, B_), 256, ATTN_SMEM_BYTES>>>(q, k, v, att);

    // Output projection (tensor cores)
    split_kernel<<<(M_*NQ_ + 255)/256, 256>>>(att, ahi, alo, M_*NQ_);
    gemm_bf16x3<<<dim3(D_/128, M_/128), 256, GEMM_SMEM>>>(ahi, alo, owhi, owlo, out, M_, D_, D_);
}

// round 8
// speedup vs baseline: 2.5217x; 1.6335x over previous
#include <cuda_runtime.h>
#include <cuda_bf16.h>
#include <cstdint>

// Problem constants
#define B_  2
#define T_  2048
#define D_  2048
#define H_  16
#define HKV_ 4
#define DH_ 128
#define M_  (B_*T_)
#define NQ_ (H_*DH_)
#define NKV_ (HKV_*DH_)

// fp32 scratch
__device__ float g_q[(size_t)M_ * NQ_];
__device__ float g_k[(size_t)M_ * NKV_];
__device__ float g_v[(size_t)M_ * NKV_];

// bf16 split scratch
__device__ __nv_bfloat16 g_xhi[(size_t)M_ * D_],  g_xlo[(size_t)M_ * D_];
__device__ __nv_bfloat16 g_qwhi[(size_t)NQ_ * D_], g_qwlo[(size_t)NQ_ * D_];
__device__ __nv_bfloat16 g_kwhi[(size_t)NKV_ * D_], g_kwlo[(size_t)NKV_ * D_];
__device__ __nv_bfloat16 g_vwhi[(size_t)NKV_ * D_], g_vwlo[(size_t)NKV_ * D_];
__device__ __nv_bfloat16 g_owhi[(size_t)D_ * D_],  g_owlo[(size_t)D_ * D_];
__device__ __nv_bfloat16 g_ahi[(size_t)M_ * NQ_],  g_alo[(size_t)M_ * NQ_];

// ---------------------------------------------------------------------------
__device__ __forceinline__ void cp_async16(uint32_t s, const void* g) {
    asm volatile("cp.async.cg.shared.global [%0], [%1], 16;\n" :: "r"(s), "l"(g));
}
__device__ __forceinline__ void cp_commit() {
    asm volatile("cp.async.commit_group;\n");
}
template<int N> __device__ __forceinline__ void cp_wait() {
    asm volatile("cp.async.wait_group %0;\n" :: "n"(N));
}
__device__ __forceinline__ void ldsm_x4(uint32_t& r0, uint32_t& r1,
                                        uint32_t& r2, uint32_t& r3, uint32_t a) {
    asm volatile("ldmatrix.sync.aligned.m8n8.x4.shared.b16 {%0,%1,%2,%3}, [%4];\n"
                 : "=r"(r0), "=r"(r1), "=r"(r2), "=r"(r3) : "r"(a));
}
__device__ __forceinline__ void mma_bf16(float* d, const uint32_t* a,
                                         uint32_t b0, uint32_t b1) {
    asm volatile(
        "mma.sync.aligned.m16n8k16.row.col.f32.bf16.bf16.f32 "
        "{%0,%1,%2,%3},{%4,%5,%6,%7},{%8,%9},{%0,%1,%2,%3};\n"
        : "+f"(d[0]), "+f"(d[1]), "+f"(d[2]), "+f"(d[3])
        : "r"(a[0]), "r"(a[1]), "r"(a[2]), "r"(a[3]), "r"(b0), "r"(b1));
}
__device__ __forceinline__ void mma_tf32(float* d, const uint32_t* a,
                                         uint32_t b0, uint32_t b1) {
    asm volatile(
        "mma.sync.aligned.m16n8k8.row.col.f32.tf32.tf32.f32 "
        "{%0,%1,%2,%3},{%4,%5,%6,%7},{%8,%9},{%0,%1,%2,%3};\n"
        : "+f"(d[0]), "+f"(d[1]), "+f"(d[2]), "+f"(d[3])
        : "r"(a[0]), "r"(a[1]), "r"(a[2]), "r"(a[3]), "r"(b0), "r"(b1));
}
__device__ __forceinline__ uint32_t f2tf32(float x) {
    uint32_t r;
    asm("cvt.rna.tf32.f32 %0, %1;" : "=r"(r) : "f"(x));
    return r;
}
__device__ __forceinline__ float tf32r(float x) { return __uint_as_float(f2tf32(x)); }
__device__ __forceinline__ float fexp2(float x) {
    float y;
    asm("ex2.approx.ftz.f32 %0, %1;" : "=f"(y) : "f"(x));
    return y;
}

// ---------------------------------------------------------------------------
__global__ __launch_bounds__(256) void split_kernel(
    const float* __restrict__ in, __nv_bfloat16* __restrict__ hi,
    __nv_bfloat16* __restrict__ lo, int n)
{
    int i = blockIdx.x * blockDim.x + threadIdx.x;
    if (i < n) {
        float v = in[i];
        __nv_bfloat16 h = __float2bfloat16(v);
        hi[i] = h;
        lo[i] = __float2bfloat16(v - __bfloat162float(h));
    }
}

// ---------------------------------------------------------------------------
// bf16x3 NT GEMM (proven)
// ---------------------------------------------------------------------------
#define BK_G   32
#define LDSR   40
#define TILE_E (128*LDSR)
#define TILE_B (TILE_E*2)
#define STAGE_B (4*TILE_B)
#define GEMM_SMEM (2*STAGE_B)

__device__ __forceinline__ void gemm_load_stage(
    uint32_t sa, const __nv_bfloat16* Ahi, const __nv_bfloat16* Alo,
    const __nv_bfloat16* Whi, const __nv_bfloat16* Wlo,
    int bm, int bn, int K, int k0, int tid)
{
#pragma unroll
    for (int half = 0; half < 2; half++) {
        const int idx = tid + half * 256;
        const int row = idx >> 2;
        const int c8  = (idx & 3) << 3;
        const size_t ga = (size_t)(bm + row) * K + k0 + c8;
        const size_t gw = (size_t)(bn + row) * K + k0 + c8;
        const uint32_t so = (uint32_t)(row * LDSR + c8) * 2;
        cp_async16(sa +            so, Ahi + ga);
        cp_async16(sa + TILE_B   + so, Alo + ga);
        cp_async16(sa + 2*TILE_B + so, Whi + gw);
        cp_async16(sa + 3*TILE_B + so, Wlo + gw);
    }
}

__global__ __launch_bounds__(256) void gemm_bf16x3(
    const __nv_bfloat16* __restrict__ Ahi, const __nv_bfloat16* __restrict__ Alo,
    const __nv_bfloat16* __restrict__ Whi, const __nv_bfloat16* __restrict__ Wlo,
    float* __restrict__ C, int M, int N, int K)
{
    extern __shared__ __nv_bfloat16 smg[];
    const int tid  = threadIdx.x;
    const int warp = tid >> 5, lane = tid & 31;
    const int wm = (warp >> 2) * 64;
    const int wn = (warp & 3) * 32;
    const int bm = blockIdx.y * 128;
    const int bn = blockIdx.x * 128;
    const uint32_t sbase = (uint32_t)__cvta_generic_to_shared(smg);

    float acc[4][4][4];
#pragma unroll
    for (int i = 0; i < 4; i++)
#pragma unroll
        for (int j = 0; j < 4; j++)
#pragma unroll
            for (int r = 0; r < 4; r++) acc[i][j][r] = 0.f;

    const int arow = (lane & 7) + ((lane >> 3) & 1) * 8;
    const int acb  = ((lane >> 4) & 1) * 16;
    const int brow = (lane & 7) + ((lane >> 4) & 1) * 8;
    const int bcb  = ((lane >> 3) & 1) * 16;

    gemm_load_stage(sbase, Ahi, Alo, Whi, Wlo, bm, bn, K, 0, tid);
    cp_commit();

    const int NC = K / BK_G;
    for (int c = 0; c < NC; c++) {
        if (c + 1 < NC) {
            gemm_load_stage(sbase + ((c + 1) & 1) * STAGE_B,
                            Ahi, Alo, Whi, Wlo, bm, bn, K, (c + 1) * BK_G, tid);
            cp_commit();
            cp_wait<1>();
        } else {
            cp_wait<0>();
        }
        __syncthreads();

        const uint32_t base = sbase + (c & 1) * STAGE_B;
        const uint32_t aAhi = base;
        const uint32_t aAlo = base + TILE_B;
        const uint32_t aWhi = base + 2*TILE_B;
        const uint32_t aWlo = base + 3*TILE_B;

#pragma unroll
        for (int kh = 0; kh < 2; kh++) {
            const int kb = kh * 32;
            uint32_t bhi[4][2], blo[4][2];
#pragma unroll
            for (int jj = 0; jj < 2; jj++) {
                uint32_t ad = aWhi + (uint32_t)((wn + jj*16 + brow) * LDSR) * 2 + bcb + kb;
                ldsm_x4(bhi[2*jj][0], bhi[2*jj][1], bhi[2*jj+1][0], bhi[2*jj+1][1], ad);
                ad = aWlo + (uint32_t)((wn + jj*16 + brow) * LDSR) * 2 + bcb + kb;
                ldsm_x4(blo[2*jj][0], blo[2*jj][1], blo[2*jj+1][0], blo[2*jj+1][1], ad);
            }
            uint32_t a[4][4];
#pragma unroll
            for (int i = 0; i < 4; i++) {
                uint32_t ad = aAhi + (uint32_t)((wm + i*16 + arow) * LDSR) * 2 + acb + kb;
                ldsm_x4(a[i][0], a[i][1], a[i][2], a[i][3], ad);
            }
#pragma unroll
            for (int i = 0; i < 4; i++)
#pragma unroll
                for (int j = 0; j < 4; j++) {
                    mma_bf16(acc[i][j], a[i], bhi[j][0], bhi[j][1]);
                    mma_bf16(acc[i][j], a[i], blo[j][0], blo[j][1]);
                }
#pragma unroll
            for (int i = 0; i < 4; i++) {
                uint32_t ad = aAlo + (uint32_t)((wm + i*16 + arow) * LDSR) * 2 + acb + kb;
                ldsm_x4(a[i][0], a[i][1], a[i][2], a[i][3], ad);
            }
#pragma unroll
            for (int i = 0; i < 4; i++)
#pragma unroll
                for (int j = 0; j < 4; j++)
                    mma_bf16(acc[i][j], a[i], bhi[j][0], bhi[j][1]);
        }
        __syncthreads();
    }

    const int er = lane >> 2, ec = (lane & 3) * 2;
#pragma unroll
    for (int i = 0; i < 4; i++)
#pragma unroll
        for (int j = 0; j < 4; j++) {
            float* p0 = C + (size_t)(bm + wm + 16*i + er) * N + bn + wn + 8*j + ec;
            float* p1 = p0 + (size_t)8 * N;
            *(float2*)p0 = make_float2(acc[i][j][0], acc[i][j][1]);
            *(float2*)p1 = make_float2(acc[i][j][2], acc[i][j][3]);
        }
}

// ---------------------------------------------------------------------------
// RoPE + scale fold + round-to-TF32 in place on q, k, v.
// q *= temp[h] * (1/sqrt(DH)) * log2(e)  -> softmax uses exp2.
// ---------------------------------------------------------------------------
__global__ __launch_bounds__(256) void rope_tf32(
    float* __restrict__ q, float* __restrict__ k, float* __restrict__ v,
    const float* __restrict__ cosb, const float* __restrict__ sinb,
    const float* __restrict__ temp)
{
    const int token = blockIdx.x;
    const int t = token & (T_ - 1);
    const float SC = 0.08838834764831845f * 1.4426950408889634f;
    for (int s = threadIdx.x; s < 1536; s += blockDim.x) {
        const int head = s >> 6;
        const int i = s & 63;
        float* base;
        float scale = 1.0f;
        bool dorope = true;
        if (head < 16) {
            base = q + ((size_t)token * H_ + head) * DH_;
            scale = temp[head] * SC;
        } else if (head < 20) {
            base = k + ((size_t)token * HKV_ + (head - 16)) * DH_;
        } else {
            base = v + ((size_t)token * HKV_ + (head - 20)) * DH_;
            dorope = false;
        }
        if (dorope && i < 32) {
            const float c  = cosb[t*32 + i];
            const float sn = sinb[t*32 + i];
            const float x1 = base[2*i];
            const float x2 = base[2*i + 1];
            base[2*i]     = tf32r((x1*c - x2*sn) * scale);
            base[2*i + 1] = tf32r((x1*sn + x2*c) * scale);
        } else {
            const int d = dorope ? 64 + (i - 32) * 2 : i * 2;
            base[d]     = tf32r(base[d] * scale);
            base[d + 1] = tf32r(base[d + 1] * scale);
        }
    }
}

// ---------------------------------------------------------------------------
// TF32 tensor-core causal GQA flash attention.
// BQ=128 (8 warps x 16 rows), BK=64, DH=128.
// K double-buf (pad 132), V double-buf (pad 136), P via smem (pad 68).
// Epilogue writes bf16 hi/lo split directly.
// ---------------------------------------------------------------------------
#define KOFF0 0
#define KOFF1 8448
#define VOFF0 16896
#define VOFF1 25600
#define POFF  34304
#define ATTN_SMEM_B ((POFF + 8704) * 4)   // 172032 bytes

__global__ __launch_bounds__(256, 1) void attn_tc(
    const float* __restrict__ Qg, const float* __restrict__ Kg,
    const float* __restrict__ Vg,
    __nv_bfloat16* __restrict__ Ahi, __nv_bfloat16* __restrict__ Alo)
{
    extern __shared__ float sm[];
    const uint32_t sbase = (uint32_t)__cvta_generic_to_shared(sm);
    const int qt = 15 - blockIdx.x;             // heavy tiles first
    const int h = blockIdx.y, b = blockIdx.z;
    const int kvh = h >> 2;
    const int tid = threadIdx.x;
    const int warp = tid >> 5, lane = tid & 31;
    const int g4 = lane >> 2, c4 = lane & 3;
    const int qrow0 = qt * 128 + warp * 16;
    const int nk = 2 * qt + 2;

    // Q fragments from gmem (already tf32-rounded + scaled by rope)
    uint32_t qf[16][4];
    {
        const float* Q0 = Qg + ((size_t)(b*T_ + qrow0 + g4)*H_ + h)*DH_;
        const float* Q1 = Q0 + (size_t)8*H_*DH_;
#pragma unroll
        for (int kc = 0; kc < 16; kc++) {
            const int c0 = kc*8 + c4;
            qf[kc][0] = __float_as_uint(__ldg(Q0 + c0));
            qf[kc][1] = __float_as_uint(__ldg(Q1 + c0));
            qf[kc][2] = __float_as_uint(__ldg(Q0 + c0 + 4));
            qf[kc][3] = __float_as_uint(__ldg(Q1 + c0 + 4));
        }
    }

    float o[16][4];
#pragma unroll
    for (int dt = 0; dt < 16; dt++)
#pragma unroll
        for (int r = 0; r < 4; r++) o[dt][r] = 0.f;
    float m0 = -1e30f, m1 = -1e30f, l0 = 0.f, l1 = 0.f;

    float* Ps = sm + POFF + warp * 1088;

    // prologue: K0, V0
    {
        const size_t kvoff = ((size_t)(b*T_)*HKV_ + kvh)*DH_;
#pragma unroll
        for (int i = 0; i < 8; i++) {
            const int idx = tid + i*256, row = idx >> 5, cc = (idx & 31)*4;
            cp_async16(sbase + (uint32_t)(KOFF0 + row*132 + cc)*4,
                       Kg + kvoff + (size_t)row*NKV_ + cc);
        }
        cp_commit();
#pragma unroll
        for (int i = 0; i < 8; i++) {
            const int idx = tid + i*256, row = idx >> 5, cc = (idx & 31)*4;
            cp_async16(sbase + (uint32_t)(VOFF0 + row*136 + cc)*4,
                       Vg + kvoff + (size_t)row*NKV_ + cc);
        }
        cp_commit();
    }

    for (int kt = 0; kt < nk; kt++) {
        const int kc0 = kt * 64;
        const bool skip = (kc0 > qrow0 + 15);
        cp_wait<1>();
        __syncthreads();

        float sacc[8][4];
        if (!skip) {
#pragma unroll
            for (int nt = 0; nt < 8; nt++)
#pragma unroll
                for (int r = 0; r < 4; r++) sacc[nt][r] = 0.f;
            const float* Ksm = sm + ((kt & 1) ? KOFF1 : KOFF0);
#pragma unroll
            for (int kc = 0; kc < 16; kc++) {
                const int dk = kc*8 + c4;
#pragma unroll
                for (int nt = 0; nt < 8; nt++) {
                    const float* kp = Ksm + (nt*8 + g4)*132 + dk;
                    mma_tf32(sacc[nt], qf[kc],
                             __float_as_uint(kp[0]), __float_as_uint(kp[4]));
                }
            }
        }

        if (kt + 1 < nk) {   // prefetch next K
            const size_t kvoff = ((size_t)(b*T_ + kc0 + 64)*HKV_ + kvh)*DH_;
            const uint32_t kb = sbase + (uint32_t)(((kt+1)&1) ? KOFF1 : KOFF0)*4;
#pragma unroll
            for (int i = 0; i < 8; i++) {
                const int idx = tid + i*256, row = idx >> 5, cc = (idx & 31)*4;
                cp_async16(kb + (uint32_t)(row*132 + cc)*4,
                           Kg + kvoff + (size_t)row*NKV_ + cc);
            }
            cp_commit();
        }

        if (!skip) {
            // mask (diagonal region only), in log2 units
            if (kc0 + 63 > qrow0) {
#pragma unroll
                for (int nt = 0; nt < 8; nt++) {
                    const int cc = kc0 + nt*8 + 2*c4;
                    const int r0 = qrow0 + g4, r1 = r0 + 8;
                    if (cc     > r0) sacc[nt][0] = -1e30f;
                    if (cc + 1 > r0) sacc[nt][1] = -1e30f;
                    if (cc     > r1) sacc[nt][2] = -1e30f;
                    if (cc + 1 > r1) sacc[nt][3] = -1e30f;
                }
            }
            // online softmax
            float rm0 = -1e30f, rm1 = -1e30f;
#pragma unroll
            for (int nt = 0; nt < 8; nt++) {
                rm0 = fmaxf(rm0, fmaxf(sacc[nt][0], sacc[nt][1]));
                rm1 = fmaxf(rm1, fmaxf(sacc[nt][2], sacc[nt][3]));
            }
#pragma unroll
            for (int off = 1; off <= 2; off <<= 1) {
                rm0 = fmaxf(rm0, __shfl_xor_sync(0xffffffffu, rm0, off));
                rm1 = fmaxf(rm1, __shfl_xor_sync(0xffffffffu, rm1, off));
            }
            const float mn0 = fmaxf(m0, rm0), mn1 = fmaxf(m1, rm1);
            const float a0 = fexp2(m0 - mn0), a1 = fexp2(m1 - mn1);
            m0 = mn0; m1 = mn1;
            float rs0 = 0.f, rs1 = 0.f;
#pragma unroll
            for (int nt = 0; nt < 8; nt++) {
                float p0 = fexp2(sacc[nt][0] - mn0);
                float p1 = fexp2(sacc[nt][1] - mn0);
                float p2 = fexp2(sacc[nt][2] - mn1);
                float p3 = fexp2(sacc[nt][3] - mn1);
                rs0 += p0 + p1; rs1 += p2 + p3;
                float* pr = Ps + g4*68 + nt*8 + 2*c4;
                *(float2*)pr = make_float2(__uint_as_float(f2tf32(p0)),
                                           __uint_as_float(f2tf32(p1)));
                *(float2*)(pr + 8*68) = make_float2(__uint_as_float(f2tf32(p2)),
                                                    __uint_as_float(f2tf32(p3)));
            }
#pragma unroll
            for (int off = 1; off <= 2; off <<= 1) {
                rs0 += __shfl_xor_sync(0xffffffffu, rs0, off);
                rs1 += __shfl_xor_sync(0xffffffffu, rs1, off);
            }
            l0 = l0 * a0 + rs0;
            l1 = l1 * a1 + rs1;
#pragma unroll
            for (int dt = 0; dt < 16; dt++) {
                o[dt][0] *= a0; o[dt][1] *= a0;
                o[dt][2] *= a1; o[dt][3] *= a1;
            }
        }

        if (kt + 1 < nk) cp_wait<1>(); else cp_wait<0>();
        __syncthreads();

        if (!skip) {
            const float* Vsm = sm + ((kt & 1) ? VOFF1 : VOFF0);
#pragma unroll
            for (int kc = 0; kc < 8; kc++) {
                uint32_t af[4];
                const float* pr = Ps + g4*68 + kc*8 + c4;
                af[0] = __float_as_uint(pr[0]);
                af[1] = __float_as_uint(pr[8*68]);
                af[2] = __float_as_uint(pr[4]);
                af[3] = __float_as_uint(pr[8*68 + 4]);
#pragma unroll
                for (int dt = 0; dt < 16; dt++) {
                    const float* vp = Vsm + (kc*8 + c4)*136 + dt*8 + g4;
                    mma_tf32(o[dt], af,
                             __float_as_uint(vp[0]), __float_as_uint(vp[4*136]));
                }
            }
        }

        if (kt + 1 < nk) {   // prefetch next V
            const size_t kvoff = ((size_t)(b*T_ + kc0 + 64)*HKV_ + kvh)*DH_;
            const uint32_t vb = sbase + (uint32_t)(((kt+1)&1) ? VOFF1 : VOFF0)*4;
#pragma unroll
            for (int i = 0; i < 8; i++) {
                const int idx = tid + i*256, row = idx >> 5, cc = (idx & 31)*4;
                cp_async16(vb + (uint32_t)(row*136 + cc)*4,
                           Vg + kvoff + (size_t)row*NKV_ + cc);
            }
            cp_commit();
        }
    }

    // epilogue: /l, bf16 hi/lo split, write to GEMM input
    const float inv0 = 1.f / l0, inv1 = 1.f / l1;
    const size_t base0 = ((size_t)(b*T_ + qrow0 + g4))*NQ_ + h*DH_ + 2*c4;
    const size_t base1 = base0 + (size_t)8*NQ_;
#pragma unroll
    for (int dt = 0; dt < 16; dt++) {
        float v0 = o[dt][0]*inv0, v1 = o[dt][1]*inv0;
        float v2 = o[dt][2]*inv1, v3 = o[dt][3]*inv1;
        __nv_bfloat162 h0, h1, lo0, lo1;
        h0.x = __float2bfloat16(v0); h0.y = __float2bfloat16(v1);
        h1.x = __float2bfloat16(v2); h1.y = __float2bfloat16(v3);
        lo0.x = __float2bfloat16(v0 - __bfloat162float(h0.x));
        lo0.y = __float2bfloat16(v1 - __bfloat162float(h0.y));
        lo1.x = __float2bfloat16(v2 - __bfloat162float(h1.x));
        lo1.y = __float2bfloat16(v3 - __bfloat162float(h1.y));
        *(__nv_bfloat162*)(Ahi + base0 + dt*8) = h0;
        *(__nv_bfloat162*)(Ahi + base1 + dt*8) = h1;
        *(__nv_bfloat162*)(Alo + base0 + dt*8) = lo0;
        *(__nv_bfloat162*)(Alo + base1 + dt*8) = lo1;
    }
}

// ---------------------------------------------------------------------------
extern "C" void kernel_launch(void* const* d_in, const int* in_sizes, int n_in,
                              void* d_out, int out_size)
{
    const float* x    = (const float*)d_in[0];
    const float* cosb = (const float*)d_in[1];
    const float* sinb = (const float*)d_in[2];
    const float* Wq   = (const float*)d_in[3];
    const float* Wk   = (const float*)d_in[4];
    const float* Wv   = (const float*)d_in[5];
    const float* Wo   = (const float*)d_in[6];
    const float* temp = (const float*)d_in[7];
    float* out = (float*)d_out;

    float *q, *k, *v;
    cudaGetSymbolAddress((void**)&q, g_q);
    cudaGetSymbolAddress((void**)&k, g_k);
    cudaGetSymbolAddress((void**)&v, g_v);

    __nv_bfloat16 *xhi, *xlo, *qwhi, *qwlo, *kwhi, *kwlo, *vwhi, *vwlo,
                  *owhi, *owlo, *ahi, *alo;
    cudaGetSymbolAddress((void**)&xhi,  g_xhi);
    cudaGetSymbolAddress((void**)&xlo,  g_xlo);
    cudaGetSymbolAddress((void**)&qwhi, g_qwhi);
    cudaGetSymbolAddress((void**)&qwlo, g_qwlo);
    cudaGetSymbolAddress((void**)&kwhi, g_kwhi);
    cudaGetSymbolAddress((void**)&kwlo, g_kwlo);
    cudaGetSymbolAddress((void**)&vwhi, g_vwhi);
    cudaGetSymbolAddress((void**)&vwlo, g_vwlo);
    cudaGetSymbolAddress((void**)&owhi, g_owhi);
    cudaGetSymbolAddress((void**)&owlo, g_owlo);
    cudaGetSymbolAddress((void**)&ahi,  g_ahi);
    cudaGetSymbolAddress((void**)&alo,  g_alo);

    cudaFuncSetAttribute(gemm_bf16x3,
                         cudaFuncAttributeMaxDynamicSharedMemorySize, GEMM_SMEM);
    cudaFuncSetAttribute(attn_tc,
                         cudaFuncAttributeMaxDynamicSharedMemorySize, ATTN_SMEM_B);

    split_kernel<<<(M_*D_ + 255)/256,   256>>>(x,  xhi,  xlo,  M_*D_);
    split_kernel<<<(NQ_*D_ + 255)/256,  256>>>(Wq, qwhi, qwlo, NQ_*D_);
    split_kernel<<<(NKV_*D_ + 255)/256, 256>>>(Wk, kwhi, kwlo, NKV_*D_);
    split_kernel<<<(NKV_*D_ + 255)/256, 256>>>(Wv, vwhi, vwlo, NKV_*D_);
    split_kernel<<<(D_*D_ + 255)/256,   256>>>(Wo, owhi, owlo, D_*D_);

    gemm_bf16x3<<<dim3(NQ_/128,  M_/128), 256, GEMM_SMEM>>>(xhi, xlo, qwhi, qwlo, q, M_, NQ_,  D_);
    gemm_bf16x3<<<dim3(NKV_/128, M_/128), 256, GEMM_SMEM>>>(xhi, xlo, kwhi, kwlo, k, M_, NKV_, D_);
    gemm_bf16x3<<<dim3(NKV_/128, M_/128), 256, GEMM_SMEM>>>(xhi, xlo, vwhi, vwlo, v, M_, NKV_, D_);

    rope_tf32<<<M_, 256>>>(q, k, v, cosb, sinb, temp);

    attn_tc<<<dim3(16, H_, B_), 256, ATTN_SMEM_B>>>(q, k, v, ahi, alo);

    gemm_bf16x3<<<dim3(D_/128, M_/128), 256, GEMM_SMEM>>>(ahi, alo, owhi, owlo, out, M_, D_, D_);
}